// round 2
// baseline (speedup 1.0000x reference)
#include <cuda_runtime.h>
#include <math.h>

// Problem constants
#define BATCH 32768
#define IN    128
#define HID   512
#define OUT   32
#define TM    64                 // rows per CTA
#define NCTA  (BATCH / TM)       // 512 CTAs

// ---- shared memory layout (floats) ----
// phi   : [0, 64*516)               33024 floats
// xs    : [33024, +64*131)           8384 floats  (reused as W2t + yrow later)
// ws    : [41408, +64*131)           8384 floats
#define PHI_STRIDE 516
#define XS_STRIDE  131
#define SM_PHI  0
#define SM_XS   (TM * PHI_STRIDE)            // 33024
#define SM_WS   (SM_XS + TM * XS_STRIDE)     // 41408
#define SM_TOT  (SM_WS + TM * XS_STRIDE)     // 49792 floats = 199168 bytes
#define SM_W2T  SM_XS                        // 16384 floats (fits in xs+ws = 16768)
#define SM_YROW (SM_XS + HID * OUT)          // 64 floats

// dense L scratch (device global: allocation-free)
__device__ float g_L[HID * HID];

// ---------- f32x2 packed helpers (Blackwell FFMA2) ----------
__device__ __forceinline__ unsigned long long pack2(float lo, float hi) {
    unsigned long long r;
    asm("mov.b64 %0, {%1, %2};" : "=l"(r) : "f"(lo), "f"(hi));
    return r;
}
__device__ __forceinline__ void fma2(unsigned long long& d,
                                     unsigned long long a,
                                     unsigned long long b) {
    asm("fma.rn.f32x2 %0, %1, %2, %0;" : "+l"(d) : "l"(a), "l"(b));
}
__device__ __forceinline__ float2 unpack2(unsigned long long v) {
    float2 f;
    asm("mov.b64 {%0, %1}, %2;" : "=f"(f.x), "=f"(f.y) : "l"(v));
    return f;
}

// ---------- kernel A: unpack packed-tril L_vars -> dense L ----------
__global__ void unpack_L_kernel(const float* __restrict__ Lv) {
    int idx = blockIdx.x * blockDim.x + threadIdx.x;
    if (idx >= HID * HID) return;
    int i = idx >> 9;
    int j = idx & (HID - 1);
    float v = 0.0f;
    if (j <= i) v = Lv[(i * (i + 1)) / 2 + j];
    g_L[idx] = v;
}

// ---------- kernel B: fused MLP + quadratic form ----------
extern __shared__ float smem[];

__global__ void __launch_bounds__(256, 1)
koopman_fused_kernel(const float* __restrict__ x,
                     const float* __restrict__ W1,
                     const float* __restrict__ b1,
                     const float* __restrict__ W2,
                     const float* __restrict__ qb,
                     const float* __restrict__ qc,
                     float* __restrict__ out) {
    const int tid = threadIdx.x;
    const int r0  = blockIdx.x * TM;

    // ================= Phase 1: phi = tanh(x @ W1^T + b1) into smem ======
    // stage x tile [64][128] -> xs (stride 131, scalar stores)
    #pragma unroll
    for (int s = 0; s < 8; ++s) {
        int idx4 = tid + 256 * s;            // 2048 float4s
        int r    = idx4 >> 5;                // 32 float4 per row
        int k4   = (idx4 & 31) << 2;
        float4 v = *(const float4*)(x + (size_t)(r0 + r) * IN + k4);
        float* dst = smem + SM_XS + r * XS_STRIDE + k4;
        dst[0] = v.x; dst[1] = v.y; dst[2] = v.z; dst[3] = v.w;
    }
    __syncthreads();

    const int tx = tid & 15;   // h-quad
    const int ty = tid >> 4;   // row-quad

    for (int hb = 0; hb < 8; ++hb) {
        const int h0 = hb * 64;
        // stage W1 block [64][128] -> ws
        #pragma unroll
        for (int s = 0; s < 8; ++s) {
            int idx4 = tid + 256 * s;
            int h    = idx4 >> 5;
            int k4   = (idx4 & 31) << 2;
            float4 v = *(const float4*)(W1 + (size_t)(h0 + h) * IN + k4);
            float* dst = smem + SM_WS + h * XS_STRIDE + k4;
            dst[0] = v.x; dst[1] = v.y; dst[2] = v.z; dst[3] = v.w;
        }
        __syncthreads();

        float acc[4][4];
        #pragma unroll
        for (int i = 0; i < 4; ++i)
            #pragma unroll
            for (int j = 0; j < 4; ++j) acc[i][j] = 0.0f;

        #pragma unroll 4
        for (int k = 0; k < IN; ++k) {
            float a[4], b[4];
            #pragma unroll
            for (int i = 0; i < 4; ++i)
                a[i] = smem[SM_XS + (ty * 4 + i) * XS_STRIDE + k];
            #pragma unroll
            for (int j = 0; j < 4; ++j)
                b[j] = smem[SM_WS + (tx * 4 + j) * XS_STRIDE + k];
            #pragma unroll
            for (int i = 0; i < 4; ++i)
                #pragma unroll
                for (int j = 0; j < 4; ++j)
                    acc[i][j] = fmaf(a[i], b[j], acc[i][j]);
        }

        #pragma unroll
        for (int j = 0; j < 4; ++j) {
            const int h = h0 + tx * 4 + j;
            const float bb = b1[h];
            #pragma unroll
            for (int i = 0; i < 4; ++i) {
                float ph = tanhf(acc[i][j] + bb);
                smem[SM_PHI + (ty * 4 + i) * PHI_STRIDE + h] = ph;
            }
        }
        __syncthreads();   // protect ws before next stage (and phi writes)
    }

    // ================= Phase 2: pi = phi @ W2^T =========================
    // stage W2 transposed into xs/ws region: W2t[i][o] = W2[o][i]
    #pragma unroll
    for (int s = 0; s < 16; ++s) {
        int idx4 = tid + 256 * s;          // 4096 float4s
        int e    = idx4 << 2;
        int o    = e >> 9;                 // / 512
        int i    = e & (HID - 1);
        float4 v = *(const float4*)(W2 + e);
        smem[SM_W2T + (i + 0) * OUT + o] = v.x;
        smem[SM_W2T + (i + 1) * OUT + o] = v.y;
        smem[SM_W2T + (i + 2) * OUT + o] = v.z;
        smem[SM_W2T + (i + 3) * OUT + o] = v.w;
    }
    __syncthreads();

    {
        const int o  = tid & 31;
        const int rg = tid >> 5;           // 8 row-groups
        float pacc[8];
        #pragma unroll
        for (int m = 0; m < 8; ++m) pacc[m] = 0.0f;

        #pragma unroll 4
        for (int i = 0; i < HID; ++i) {
            float w = smem[SM_W2T + i * OUT + o];
            #pragma unroll
            for (int m = 0; m < 8; ++m)
                pacc[m] = fmaf(smem[SM_PHI + (rg + m * 8) * PHI_STRIDE + i], w, pacc[m]);
        }
        #pragma unroll
        for (int m = 0; m < 8; ++m)
            out[(size_t)(r0 + rg + m * 8) * OUT + o] = pacc[m];
    }

    // ================= Phase 3: y = ||phi L||^2 (triangular skip) =======
    const int tx3  = tid & 7;          // j-octet within 64-wide jb tile
    const int ty3  = tid >> 3;         // 32 row-pairs
    const int row0 = ty3 * 2;
    const float* phi0 = smem + SM_PHI + row0 * PHI_STRIDE;
    const float* phi1 = phi0 + PHI_STRIDE;

    float ya0 = 0.0f, ya1 = 0.0f;

    #pragma unroll 1
    for (int jb = 0; jb < 8; ++jb) {
        const int j0 = jb << 6;
        const int jc = j0 + tx3 * 8;
        unsigned long long acc[8];
        #pragma unroll
        for (int p = 0; p < 8; ++p) acc[p] = 0ull;   // == (0.0f, 0.0f)

        // L[i][j] == 0 for i < j, so start at i = j0 (block-triangular skip)
        #pragma unroll 4
        for (int i = j0; i < HID; ++i) {
            float a0 = phi0[i];
            float a1 = phi1[i];
            unsigned long long A0 = pack2(a0, a0);
            unsigned long long A1 = pack2(a1, a1);
            const ulonglong2* lp = (const ulonglong2*)(g_L + (size_t)i * HID + jc);
            ulonglong2 Ba = lp[0];   // j .. j+3
            ulonglong2 Bb = lp[1];   // j+4 .. j+7
            fma2(acc[0], A0, Ba.x);
            fma2(acc[1], A0, Ba.y);
            fma2(acc[2], A0, Bb.x);
            fma2(acc[3], A0, Bb.y);
            fma2(acc[4], A1, Ba.x);
            fma2(acc[5], A1, Ba.y);
            fma2(acc[6], A1, Bb.x);
            fma2(acc[7], A1, Bb.y);
        }
        #pragma unroll
        for (int p = 0; p < 4; ++p) {
            float2 z = unpack2(acc[p]);
            ya0 += z.x * z.x + z.y * z.y;
        }
        #pragma unroll
        for (int p = 4; p < 8; ++p) {
            float2 z = unpack2(acc[p]);
            ya1 += z.x * z.x + z.y * z.y;
        }
    }

    // reduce across the 8 tx3 lanes (same warp, xor within 8-lane groups)
    #pragma unroll
    for (int m = 1; m < 8; m <<= 1) {
        ya0 += __shfl_xor_sync(0xffffffffu, ya0, m);
        ya1 += __shfl_xor_sync(0xffffffffu, ya1, m);
    }
    if (tx3 == 0) {
        smem[SM_YROW + row0]     = ya0;
        smem[SM_YROW + row0 + 1] = ya1;
    }
    __syncthreads();

    // ================= Final: vf = y + phi.qb + qc ======================
    if (tid < TM) {
        float acc = qc[0] + smem[SM_YROW + tid];
        const float* ph = smem + SM_PHI + tid * PHI_STRIDE;
        #pragma unroll 4
        for (int i = 0; i < HID; ++i)
            acc = fmaf(ph[i], qb[i], acc);
        out[(size_t)BATCH * OUT + r0 + tid] = acc;
    }
}

// ---------------------------------------------------------------------------
extern "C" void kernel_launch(void* const* d_in, const int* in_sizes, int n_in,
                              void* d_out, int out_size) {
    const float* x   = (const float*)d_in[0];
    const float* W1  = (const float*)d_in[1];
    const float* b1  = (const float*)d_in[2];
    const float* W2  = (const float*)d_in[3];
    const float* Lv  = (const float*)d_in[4];
    const float* qb  = (const float*)d_in[5];
    const float* qc  = (const float*)d_in[6];
    float* out = (float*)d_out;

    static bool attr_done = false;
    if (!attr_done) {
        cudaFuncSetAttribute(koopman_fused_kernel,
                             cudaFuncAttributeMaxDynamicSharedMemorySize,
                             SM_TOT * (int)sizeof(float));
        attr_done = true;
    }

    unpack_L_kernel<<<(HID * HID + 255) / 256, 256>>>(Lv);
    koopman_fused_kernel<<<NCTA, 256, SM_TOT * sizeof(float)>>>(
        x, W1, b1, W2, qb, qc, out);
}

// round 4
// speedup vs baseline: 1.0386x; 1.0386x over previous
#include <cuda_runtime.h>
#include <math.h>

// Problem constants
#define BATCH 32768
#define IN    128
#define HID   512
#define OUT   32
#define TM    64
#define NCTA  (BATCH / TM)     // 512
#define NT    512              // threads per CTA

typedef unsigned long long ull;

// ---- shared memory layout (floats) ----
#define PHIT_STRIDE 68
#define SM_PHIT 0                                   // phiT[512][68]  (phiT[h][r])
#define SM_XST  (HID * PHIT_STRIDE)                 // 34816: xsT[128][68] (xsT[k][r])
#define SM_WST  (SM_XST + IN * PHIT_STRIDE)         // 43520: wsT[128][68] (wsT[k][h])
#define SM_W2T  SM_XST                              // reuse: W2t[512][33]
#define SM_QB   (SM_W2T + HID * 33)                 // 51712: qb[512]
#define SM_YROW (SM_QB + HID)                       // 52224: yrow[64]
#define SM_TOT  (SM_YROW + TM)                      // 52288 floats = 209152 bytes

// dense L scratch (allocation-free device global)
__device__ float g_L[HID * HID];

// ---------- packed f32x2 helpers ----------
__device__ __forceinline__ ull pack2(float lo, float hi) {
    ull r;
    asm("mov.b64 %0, {%1, %2};" : "=l"(r) : "f"(lo), "f"(hi));
    return r;
}
__device__ __forceinline__ void fma2(ull& d, ull a, ull b) {
    asm("fma.rn.f32x2 %0, %1, %2, %0;" : "+l"(d) : "l"(a), "l"(b));
}
__device__ __forceinline__ float2 unpack2(ull v) {
    float2 f;
    asm("mov.b64 {%0, %1}, %2;" : "=f"(f.x), "=f"(f.y) : "l"(v));
    return f;
}

// ---------- kernel A: unpack packed-tril L_vars -> dense L ----------
__global__ void unpack_L_kernel(const float* __restrict__ Lv) {
    int idx = blockIdx.x * blockDim.x + threadIdx.x;
    if (idx >= HID * HID) return;
    int i = idx >> 9;
    int j = idx & (HID - 1);
    float v = 0.0f;
    if (j <= i) v = Lv[(i * (i + 1)) / 2 + j];
    g_L[idx] = v;
}

// ---------- kernel B: fused MLP + quadratic form ----------
extern __shared__ float smem[];

__global__ void __launch_bounds__(NT, 1)
koopman_fused_kernel(const float* __restrict__ x,
                     const float* __restrict__ W1,
                     const float* __restrict__ b1,
                     const float* __restrict__ W2,
                     const float* __restrict__ qb,
                     const float* __restrict__ qc,
                     float* __restrict__ out) {
    const int tid = threadIdx.x;
    const int r0  = blockIdx.x * TM;

    // ============ Phase 0: stage x transposed: xsT[k][r] ============
    #pragma unroll
    for (int s = 0; s < 4; ++s) {
        int idx4 = tid + NT * s;            // 2048 float4 loads
        int r    = idx4 & 63;
        int kq   = idx4 >> 6;               // 0..31
        float4 v = *(const float4*)(x + (size_t)(r0 + r) * IN + kq * 4);
        smem[SM_XST + (kq * 4 + 0) * PHIT_STRIDE + r] = v.x;
        smem[SM_XST + (kq * 4 + 1) * PHIT_STRIDE + r] = v.y;
        smem[SM_XST + (kq * 4 + 2) * PHIT_STRIDE + r] = v.z;
        smem[SM_XST + (kq * 4 + 3) * PHIT_STRIDE + r] = v.w;
    }
    __syncthreads();

    // ============ Phase 1: phi = tanh(x @ W1^T + b1) -> phiT ============
    const int tx = tid & 31;     // h-pair: h = h0 + tx*2
    const int ty = tid >> 5;     // 16 groups x 4 rows (uniform per warp)

    for (int hb = 0; hb < 8; ++hb) {
        const int h0 = hb * 64;
        // stage wsT[k][h] for this 64-h block
        #pragma unroll
        for (int s = 0; s < 4; ++s) {
            int idx4 = tid + NT * s;
            int hh   = idx4 & 63;
            int kq   = idx4 >> 6;
            float4 v = *(const float4*)(W1 + (size_t)(h0 + hh) * IN + kq * 4);
            smem[SM_WST + (kq * 4 + 0) * PHIT_STRIDE + hh] = v.x;
            smem[SM_WST + (kq * 4 + 1) * PHIT_STRIDE + hh] = v.y;
            smem[SM_WST + (kq * 4 + 2) * PHIT_STRIDE + hh] = v.z;
            smem[SM_WST + (kq * 4 + 3) * PHIT_STRIDE + hh] = v.w;
        }
        __syncthreads();

        ull acc00 = 0ull, acc10 = 0ull, acc01 = 0ull, acc11 = 0ull;
        #pragma unroll 8
        for (int k = 0; k < IN; ++k) {
            // row pairs (natural packing, no MOVs)
            ulonglong2 ap = *(const ulonglong2*)(smem + SM_XST + k * PHIT_STRIDE + ty * 4);
            float2 b2 = *(const float2*)(smem + SM_WST + k * PHIT_STRIDE + tx * 2);
            ull B0 = pack2(b2.x, b2.x);
            ull B1 = pack2(b2.y, b2.y);
            fma2(acc00, ap.x, B0);
            fma2(acc10, ap.y, B0);
            fma2(acc01, ap.x, B1);
            fma2(acc11, ap.y, B1);
        }

        const int h  = h0 + tx * 2;
        const int rr = ty * 4;
        const float bb0 = b1[h], bb1 = b1[h + 1];
        float2 z;
        z = unpack2(acc00);
        smem[SM_PHIT + h * PHIT_STRIDE + rr + 0] = tanhf(z.x + bb0);
        smem[SM_PHIT + h * PHIT_STRIDE + rr + 1] = tanhf(z.y + bb0);
        z = unpack2(acc10);
        smem[SM_PHIT + h * PHIT_STRIDE + rr + 2] = tanhf(z.x + bb0);
        smem[SM_PHIT + h * PHIT_STRIDE + rr + 3] = tanhf(z.y + bb0);
        z = unpack2(acc01);
        smem[SM_PHIT + (h + 1) * PHIT_STRIDE + rr + 0] = tanhf(z.x + bb1);
        smem[SM_PHIT + (h + 1) * PHIT_STRIDE + rr + 1] = tanhf(z.y + bb1);
        z = unpack2(acc11);
        smem[SM_PHIT + (h + 1) * PHIT_STRIDE + rr + 2] = tanhf(z.x + bb1);
        smem[SM_PHIT + (h + 1) * PHIT_STRIDE + rr + 3] = tanhf(z.y + bb1);
        __syncthreads();
    }

    // ============ stage W2 transposed (W2t[i][o]) + qb + zero yrow ============
    #pragma unroll
    for (int s = 0; s < 8; ++s) {
        int idx4 = tid + NT * s;            // 4096 float4 loads
        int o    = idx4 >> 7;               // 0..31
        int i4   = (idx4 & 127) << 2;
        float4 v = *(const float4*)(W2 + (size_t)o * HID + i4);
        smem[SM_W2T + (i4 + 0) * 33 + o] = v.x;
        smem[SM_W2T + (i4 + 1) * 33 + o] = v.y;
        smem[SM_W2T + (i4 + 2) * 33 + o] = v.z;
        smem[SM_W2T + (i4 + 3) * 33 + o] = v.w;
    }
    smem[SM_QB + tid] = qb[tid];
    if (tid < TM) smem[SM_YROW + tid] = 0.0f;
    __syncthreads();

    // ============ Phase 2: pi = phi @ W2^T ============
    {
        const int o  = tid & 31;
        const int rg = tid >> 5;            // 16 groups x 4 rows
        ull p0 = 0ull, p1 = 0ull;
        #pragma unroll 4
        for (int i = 0; i < HID; ++i) {
            float w = smem[SM_W2T + i * 33 + o];
            ull W = pack2(w, w);
            ulonglong2 ap = *(const ulonglong2*)(smem + SM_PHIT + i * PHIT_STRIDE + rg * 4);
            fma2(p0, ap.x, W);
            fma2(p1, ap.y, W);
        }
        float2 z0 = unpack2(p0), z1 = unpack2(p1);
        float* ob = out + (size_t)(r0 + rg * 4) * OUT + o;
        ob[0 * OUT] = z0.x;
        ob[1 * OUT] = z0.y;
        ob[2 * OUT] = z1.x;
        ob[3 * OUT] = z1.y;
    }

    // ============ Phase 3: y = ||phi L||^2 (block-triangular skip) ============
    {
        const int gid = tid >> 7;           // 4 groups of 128 threads
        const int t   = tid & 127;
        const int tx3 = t & 7;              // 8 j-octets (64 j per jb)
        const int ty3 = t >> 3;             // 16 groups x 4 rows
        const int row = ty3 * 4;

        float ya0 = 0.f, ya1 = 0.f, ya2 = 0.f, ya3 = 0.f;

        #pragma unroll
        for (int pass = 0; pass < 2; ++pass) {
            const int jb = pass ? (7 - gid) : gid;   // balanced: 576 i-iters total
            const int jc = jb * 64 + tx3 * 8;
            ull acc[4][4];
            #pragma unroll
            for (int a = 0; a < 4; ++a)
                #pragma unroll
                for (int b = 0; b < 4; ++b) acc[a][b] = 0ull;

            #pragma unroll 2
            for (int i = jb * 64; i < HID; ++i) {
                const float* Lr = g_L + (size_t)i * HID + jc;
                ulonglong2 B0 = *(const ulonglong2*)(Lr);      // j..j+3
                ulonglong2 B1 = *(const ulonglong2*)(Lr + 4);  // j+4..j+7
                float4 ph = *(const float4*)(smem + SM_PHIT + i * PHIT_STRIDE + row);
                ull A;
                A = pack2(ph.x, ph.x);
                fma2(acc[0][0], A, B0.x); fma2(acc[0][1], A, B0.y);
                fma2(acc[0][2], A, B1.x); fma2(acc[0][3], A, B1.y);
                A = pack2(ph.y, ph.y);
                fma2(acc[1][0], A, B0.x); fma2(acc[1][1], A, B0.y);
                fma2(acc[1][2], A, B1.x); fma2(acc[1][3], A, B1.y);
                A = pack2(ph.z, ph.z);
                fma2(acc[2][0], A, B0.x); fma2(acc[2][1], A, B0.y);
                fma2(acc[2][2], A, B1.x); fma2(acc[2][3], A, B1.y);
                A = pack2(ph.w, ph.w);
                fma2(acc[3][0], A, B0.x); fma2(acc[3][1], A, B0.y);
                fma2(acc[3][2], A, B1.x); fma2(acc[3][3], A, B1.y);
            }
            #pragma unroll
            for (int b = 0; b < 4; ++b) {
                float2 z;
                z = unpack2(acc[0][b]); ya0 += z.x * z.x + z.y * z.y;
                z = unpack2(acc[1][b]); ya1 += z.x * z.x + z.y * z.y;
                z = unpack2(acc[2][b]); ya2 += z.x * z.x + z.y * z.y;
                z = unpack2(acc[3][b]); ya3 += z.x * z.x + z.y * z.y;
            }
        }

        // reduce across the 8 tx3 lanes
        #pragma unroll
        for (int m = 1; m < 8; m <<= 1) {
            ya0 += __shfl_xor_sync(0xffffffffu, ya0, m);
            ya1 += __shfl_xor_sync(0xffffffffu, ya1, m);
            ya2 += __shfl_xor_sync(0xffffffffu, ya2, m);
            ya3 += __shfl_xor_sync(0xffffffffu, ya3, m);
        }
        if (tx3 == 0) {
            atomicAdd(&smem[SM_YROW + row + 0], ya0);
            atomicAdd(&smem[SM_YROW + row + 1], ya1);
            atomicAdd(&smem[SM_YROW + row + 2], ya2);
            atomicAdd(&smem[SM_YROW + row + 3], ya3);
        }
    }
    __syncthreads();

    // ============ Phase 4: vf = y + phi.qb + qc ============
    {
        const int r   = tid >> 3;           // 64 rows
        const int seg = tid & 7;            // 8 segments of 64 i
        const int i0  = seg * 64;
        float acc = 0.0f;
        #pragma unroll 8
        for (int ii = 0; ii < 64; ++ii) {
            int i = i0 + ii;
            acc = fmaf(smem[SM_PHIT + i * PHIT_STRIDE + r], smem[SM_QB + i], acc);
        }
        #pragma unroll
        for (int m = 1; m < 8; m <<= 1)
            acc += __shfl_xor_sync(0xffffffffu, acc, m);
        if (seg == 0)
            out[(size_t)BATCH * OUT + r0 + r] = acc + smem[SM_YROW + r] + qc[0];
    }
}

// ---------------------------------------------------------------------------
extern "C" void kernel_launch(void* const* d_in, const int* in_sizes, int n_in,
                              void* d_out, int out_size) {
    const float* x   = (const float*)d_in[0];
    const float* W1  = (const float*)d_in[1];
    const float* b1  = (const float*)d_in[2];
    const float* W2  = (const float*)d_in[3];
    const float* Lv  = (const float*)d_in[4];
    const float* qb  = (const float*)d_in[5];
    const float* qc  = (const float*)d_in[6];
    float* out = (float*)d_out;

    static bool attr_done = false;
    if (!attr_done) {
        cudaFuncSetAttribute(koopman_fused_kernel,
                             cudaFuncAttributeMaxDynamicSharedMemorySize,
                             SM_TOT * (int)sizeof(float));
        attr_done = true;
    }

    unpack_L_kernel<<<(HID * HID + 255) / 256, 256>>>(Lv);
    koopman_fused_kernel<<<NCTA, NT, SM_TOT * sizeof(float)>>>(
        x, W1, b1, W2, qb, qc, out);
}

// round 8
// speedup vs baseline: 4.5966x; 4.4256x over previous
#include <cuda_runtime.h>
#include <cuda_bf16.h>
#include <stdint.h>

#define BATCH 32768
#define TM    64
#define NCTA  512
#define NT    256

// ---- smem byte offsets ----
#define PHIH 0            // phi_hi [64][512] bf16, 1024B rows, swizzled
#define PHIL 65536
#define XH   131072       // x_hi [64][128] bf16, 256B rows
#define XL   147456
#define WH   163840       // B staging hi (up to 128 rows x 256B)
#define WL   196608       // B staging lo
#define W2LO (WH + 10240) // phase-2 lo region (40 rows x 256B)
#define YS   229376       // y[64] float
#define SMEM_TOTAL 229632

// ---- pre-split smem-image operand tiles (device globals: allocation-free) ----
__device__ uint4 g_xh[524288], g_xl[524288];   // [512 blk][16KB image]
__device__ uint4 g_w1h[8192],  g_w1l[8192];    // [4 chunk][32KB image] (h-rows x k)
__device__ uint4 g_lth[32768], g_ltl[32768];   // [16 tile][32KB image] L^T[j][i]
__device__ uint4 g_w2[5120];                   // [4 chunk][hi 10KB | lo 10KB] W2ext 40xk

// XOR swizzle: 16B unit index ^ (row & 7); conflict-free ldmatrix
__device__ __forceinline__ uint32_t swu(int row, int unit, int rb) {
    return (uint32_t)(row * rb) + (uint32_t)((unit ^ (row & 7)) << 4);
}
__device__ __forceinline__ void split_bf16(float v, uint32_t& h, uint32_t& l) {
    __nv_bfloat16 hb = __float2bfloat16(v);
    float r = v - __bfloat162float(hb);
    __nv_bfloat16 lb = __float2bfloat16(r);
    h = (uint32_t)__bfloat16_as_ushort(hb);
    l = (uint32_t)__bfloat16_as_ushort(lb);
}
__device__ __forceinline__ void split8(const float* v, uint4& hv, uint4& lv) {
    uint32_t hw[8], lw[8];
    #pragma unroll
    for (int q = 0; q < 8; ++q) split_bf16(v[q], hw[q], lw[q]);
    hv = make_uint4(hw[0] | (hw[1] << 16), hw[2] | (hw[3] << 16),
                    hw[4] | (hw[5] << 16), hw[6] | (hw[7] << 16));
    lv = make_uint4(lw[0] | (lw[1] << 16), lw[2] | (lw[3] << 16),
                    lw[4] | (lw[5] << 16), lw[6] | (lw[7] << 16));
}

// ---- ldmatrix / mma wrappers (baseline PTX ISA, compiles for sm_103) ----
__device__ __forceinline__ void ldsm_x4(uint32_t a, uint32_t* r) {
    asm volatile("ldmatrix.sync.aligned.m8n8.x4.shared.b16 {%0,%1,%2,%3}, [%4];"
                 : "=r"(r[0]), "=r"(r[1]), "=r"(r[2]), "=r"(r[3]) : "r"(a));
}
__device__ __forceinline__ void ldsm_x2(uint32_t a, uint32_t* r) {
    asm volatile("ldmatrix.sync.aligned.m8n8.x2.shared.b16 {%0,%1}, [%2];"
                 : "=r"(r[0]), "=r"(r[1]) : "r"(a));
}
__device__ __forceinline__ void mma16816(float* c, const uint32_t* a, const uint32_t* b) {
    asm volatile("mma.sync.aligned.m16n8k16.row.col.f32.bf16.bf16.f32 "
                 "{%0,%1,%2,%3}, {%4,%5,%6,%7}, {%8,%9}, {%0,%1,%2,%3};"
                 : "+f"(c[0]), "+f"(c[1]), "+f"(c[2]), "+f"(c[3])
                 : "r"(a[0]), "r"(a[1]), "r"(a[2]), "r"(a[3]), "r"(b[0]), "r"(b[1]));
}

// ---- prep kernels: split fp32 -> bf16 hi/lo smem-image tiles ----
__global__ void prep_x(const float* __restrict__ x) {
    int u = blockIdx.x * 256 + threadIdx.x;          // 524288 units
    int rg = u >> 4, c0 = (u & 15) << 3;
    const float* s = x + (size_t)rg * 128 + c0;
    float v[8];
    #pragma unroll
    for (int q = 0; q < 8; ++q) v[q] = s[q];
    uint4 hv, lv; split8(v, hv, lv);
    uint32_t off = ((uint32_t)((rg >> 6) * 16384) + swu(rg & 63, c0 >> 3, 256)) >> 4;
    g_xh[off] = hv; g_xl[off] = lv;
}
__global__ void prep_w1(const float* __restrict__ W1) {
    int u = blockIdx.x * 256 + threadIdx.x;          // 8192 units
    int h = u >> 4, c0 = (u & 15) << 3;
    const float* s = W1 + (size_t)h * 128 + c0;
    float v[8];
    #pragma unroll
    for (int q = 0; q < 8; ++q) v[q] = s[q];
    uint4 hv, lv; split8(v, hv, lv);
    uint32_t off = ((uint32_t)((h >> 7) * 32768) + swu(h & 127, c0 >> 3, 256)) >> 4;
    g_w1h[off] = hv; g_w1l[off] = lv;
}
__global__ void prep_lt(const float* __restrict__ Lv) {
    int u = blockIdx.x * 256 + threadIdx.x;          // 32768 units
    int tile = u >> 11;
    int r = (u >> 4) & 127, c0 = (u & 15) << 3;
    int t = tile >> 2, kt = tile & 3;
    int j = t * 128 + r;
    float v[8];
    #pragma unroll
    for (int q = 0; q < 8; ++q) {
        int i = kt * 128 + c0 + q;
        v[q] = (j <= i) ? Lv[i * (i + 1) / 2 + j] : 0.0f;    // L^T[j][i]
    }
    uint4 hv, lv; split8(v, hv, lv);
    uint32_t off = ((uint32_t)(tile * 32768) + swu(r, c0 >> 3, 256)) >> 4;
    g_lth[off] = hv; g_ltl[off] = lv;
}
__global__ void prep_w2(const float* __restrict__ W2, const float* __restrict__ qb) {
    int u = blockIdx.x * 256 + threadIdx.x;          // 2560 units
    if (u >= 2560) return;
    int chunk = u / 640, g = u - chunk * 640;
    int o = g >> 4, c0 = (g & 15) << 3;
    float v[8];
    #pragma unroll
    for (int q = 0; q < 8; ++q) {
        int i = chunk * 128 + c0 + q;
        v[q] = (o < 32) ? W2[(size_t)o * 512 + i] : ((o == 32) ? qb[i] : 0.0f);
    }
    uint4 hv, lv; split8(v, hv, lv);
    uint32_t off = (uint32_t)(chunk * 1280) + (swu(o, c0 >> 3, 256) >> 4);
    g_w2[off] = hv; g_w2[off + 640] = lv;
}

// ---- main fused kernel ----
__global__ void __launch_bounds__(NT, 1)
koopman_hmma(const float* __restrict__ b1, const float* __restrict__ qc,
             float* __restrict__ out) {
    extern __shared__ char sm[];
    const int tid = threadIdx.x, lane = tid & 31, warp = tid >> 5;
    const int blk = blockIdx.x, r0 = blk * TM;
    const int mw = warp & 3, nh = warp >> 2;
    const int m0 = mw * 16;
    const int arow = m0 + (lane & 7) + (((lane >> 3) & 1) << 3);
    const int acb  = lane >> 4;
    const int brow = lane & 7;
    const int bcb  = (lane >> 3) & 1;
    const int r1 = m0 + (lane >> 2), r2 = r1 + 8;
    const uint32_t smb = (uint32_t)__cvta_generic_to_shared(sm);
    float* ys = (float*)(sm + YS);

    if (tid < TM) ys[tid] = 0.0f;
    {   // stage x hi/lo
        const uint4* sxh = g_xh + (size_t)blk * 1024;
        const uint4* sxl = g_xl + (size_t)blk * 1024;
        uint4* dh = (uint4*)(sm + XH);
        uint4* dl = (uint4*)(sm + XL);
        for (int i = tid; i < 1024; i += NT) { dh[i] = sxh[i]; dl[i] = sxl[i]; }
    }
    __syncthreads();

    // ============ Phase 1: phi = tanh(x @ W1^T + b1) ============
    for (int c = 0; c < 4; ++c) {
        if (c) __syncthreads();
        {
            const uint4* swh = g_w1h + c * 2048;
            const uint4* swl = g_w1l + c * 2048;
            uint4* dh = (uint4*)(sm + WH);
            uint4* dl = (uint4*)(sm + WL);
            for (int i = tid; i < 2048; i += NT) { dh[i] = swh[i]; dl[i] = swl[i]; }
        }
        __syncthreads();

        float acc[8][4];
        #pragma unroll
        for (int nt = 0; nt < 8; ++nt)
            #pragma unroll
            for (int q = 0; q < 4; ++q) acc[nt][q] = 0.0f;

        #pragma unroll 2
        for (int k8 = 0; k8 < 8; ++k8) {
            const int ku = k8 * 2;
            uint32_t ah[4], al[4];
            uint32_t ao = smb + XH + swu(arow, ku + acb, 256);
            ldsm_x4(ao, ah);
            ldsm_x4(ao + (XL - XH), al);
            #pragma unroll
            for (int nt = 0; nt < 8; ++nt) {
                int bn = nh * 64 + nt * 8 + brow;
                uint32_t bo = smb + WH + swu(bn, ku + bcb, 256);
                uint32_t bh[2], bl[2];
                ldsm_x2(bo, bh);
                ldsm_x2(bo + (WL - WH), bl);
                mma16816(acc[nt], ah, bh);
                mma16816(acc[nt], al, bh);
                mma16816(acc[nt], ah, bl);
            }
        }
        // epilogue: +b1, tanh, split, store phi hi/lo
        #pragma unroll
        for (int nt = 0; nt < 8; ++nt) {
            int h = c * 128 + nh * 64 + nt * 8 + (lane & 3) * 2;
            float bb0 = __ldg(b1 + h), bb1 = __ldg(b1 + h + 1);
            float v0 = tanhf(acc[nt][0] + bb0), v1 = tanhf(acc[nt][1] + bb1);
            float v2 = tanhf(acc[nt][2] + bb0), v3 = tanhf(acc[nt][3] + bb1);
            uint32_t h0, l0, h1, l1;
            uint32_t sub = ((uint32_t)(h & 7)) << 1;
            split_bf16(v0, h0, l0); split_bf16(v1, h1, l1);
            *(uint32_t*)(sm + PHIH + swu(r1, h >> 3, 1024) + sub) = h0 | (h1 << 16);
            *(uint32_t*)(sm + PHIL + swu(r1, h >> 3, 1024) + sub) = l0 | (l1 << 16);
            split_bf16(v2, h0, l0); split_bf16(v3, h1, l1);
            *(uint32_t*)(sm + PHIH + swu(r2, h >> 3, 1024) + sub) = h0 | (h1 << 16);
            *(uint32_t*)(sm + PHIL + swu(r2, h >> 3, 1024) + sub) = l0 | (l1 << 16);
        }
    }

    // ============ Phase 3: y = ||phi @ L||^2 (block-triangular skip) ============
    for (int t = 0; t < 4; ++t) {
        float acc[8][4];
        #pragma unroll
        for (int nt = 0; nt < 8; ++nt)
            #pragma unroll
            for (int q = 0; q < 4; ++q) acc[nt][q] = 0.0f;

        for (int kt = t; kt < 4; ++kt) {
            __syncthreads();
            {
                const uint4* slh = g_lth + (t * 4 + kt) * 2048;
                const uint4* sll = g_ltl + (t * 4 + kt) * 2048;
                uint4* dh = (uint4*)(sm + WH);
                uint4* dl = (uint4*)(sm + WL);
                for (int i = tid; i < 2048; i += NT) { dh[i] = slh[i]; dl[i] = sll[i]; }
            }
            __syncthreads();
            #pragma unroll 2
            for (int k8 = 0; k8 < 8; ++k8) {
                const int kuA = (kt * 128 + k8 * 16) >> 3;
                const int kuB = k8 * 2;
                uint32_t ah[4], al[4];
                uint32_t ao = smb + PHIH + swu(arow, kuA + acb, 1024);
                ldsm_x4(ao, ah);
                ldsm_x4(ao + (PHIL - PHIH), al);
                #pragma unroll
                for (int nt = 0; nt < 8; ++nt) {
                    int bn = nh * 64 + nt * 8 + brow;
                    uint32_t bo = smb + WH + swu(bn, kuB + bcb, 256);
                    uint32_t bh[2], bl[2];
                    ldsm_x2(bo, bh);
                    ldsm_x2(bo + (WL - WH), bl);
                    mma16816(acc[nt], ah, bh);
                    mma16816(acc[nt], al, bh);
                    mma16816(acc[nt], ah, bl);
                }
            }
        }
        float s1 = 0.0f, s2 = 0.0f;
        #pragma unroll
        for (int nt = 0; nt < 8; ++nt) {
            s1 = fmaf(acc[nt][0], acc[nt][0], s1);
            s1 = fmaf(acc[nt][1], acc[nt][1], s1);
            s2 = fmaf(acc[nt][2], acc[nt][2], s2);
            s2 = fmaf(acc[nt][3], acc[nt][3], s2);
        }
        s1 += __shfl_xor_sync(0xffffffffu, s1, 1);
        s1 += __shfl_xor_sync(0xffffffffu, s1, 2);
        s2 += __shfl_xor_sync(0xffffffffu, s2, 1);
        s2 += __shfl_xor_sync(0xffffffffu, s2, 2);
        if ((lane & 3) == 0) { atomicAdd(ys + r1, s1); atomicAdd(ys + r2, s2); }
    }

    // ============ Phase 2: [pi | phi.qb] = phi @ W2ext^T ============
    const int ntc = nh ? 2 : 3;
    float acc2[3][4];
    #pragma unroll
    for (int q = 0; q < 3; ++q)
        #pragma unroll
        for (int e = 0; e < 4; ++e) acc2[q][e] = 0.0f;

    for (int kt = 0; kt < 4; ++kt) {
        __syncthreads();
        {
            const uint4* s = g_w2 + kt * 1280;
            uint4* dh = (uint4*)(sm + WH);
            uint4* dl = (uint4*)(sm + W2LO);
            for (int i = tid; i < 640; i += NT) { dh[i] = s[i]; dl[i] = s[640 + i]; }
        }
        __syncthreads();
        #pragma unroll 2
        for (int k8 = 0; k8 < 8; ++k8) {
            const int kuA = (kt * 128 + k8 * 16) >> 3;
            const int kuB = k8 * 2;
            uint32_t ah[4], al[4];
            uint32_t ao = smb + PHIH + swu(arow, kuA + acb, 1024);
            ldsm_x4(ao, ah);
            ldsm_x4(ao + (PHIL - PHIH), al);
            #pragma unroll
            for (int q = 0; q < 3; ++q) {
                if (q >= ntc) break;
                int tile = nh ? 3 + q : q;
                int bn = tile * 8 + brow;
                uint32_t bo = smb + WH + swu(bn, kuB + bcb, 256);
                uint32_t bh[2], bl[2];
                ldsm_x2(bo, bh);
                ldsm_x2(bo + (W2LO - WH), bl);
                mma16816(acc2[q], ah, bh);
                mma16816(acc2[q], al, bh);
                mma16816(acc2[q], ah, bl);
            }
        }
    }
    __syncthreads();
    #pragma unroll
    for (int q = 0; q < 3; ++q) {
        if (q >= ntc) break;
        int tile = nh ? 3 + q : q;
        int o = tile * 8 + (lane & 3) * 2;
        if (tile < 4) {
            out[(size_t)(r0 + r1) * 32 + o]     = acc2[q][0];
            out[(size_t)(r0 + r1) * 32 + o + 1] = acc2[q][1];
            out[(size_t)(r0 + r2) * 32 + o]     = acc2[q][2];
            out[(size_t)(r0 + r2) * 32 + o + 1] = acc2[q][3];
        } else if ((lane & 3) == 0) {
            float qcv = __ldg(qc);
            out[(size_t)BATCH * 32 + r0 + r1] = ys[r1] + acc2[q][0] + qcv;
            out[(size_t)BATCH * 32 + r0 + r2] = ys[r2] + acc2[q][2] + qcv;
        }
    }
}

// ---------------------------------------------------------------------------
extern "C" void kernel_launch(void* const* d_in, const int* in_sizes, int n_in,
                              void* d_out, int out_size) {
    const float* x  = (const float*)d_in[0];
    const float* W1 = (const float*)d_in[1];
    const float* b1 = (const float*)d_in[2];
    const float* W2 = (const float*)d_in[3];
    const float* Lv = (const float*)d_in[4];
    const float* qb = (const float*)d_in[5];
    const float* qc = (const float*)d_in[6];
    float* out = (float*)d_out;

    // Set once, on the (non-captured) correctness call only. Calling
    // cudaFuncSetAttribute during graph capture is the one behavioral delta
    // vs the rounds that passed; keep it out of the captured path.
    static bool attr_done = false;
    if (!attr_done) {
        cudaFuncSetAttribute(koopman_hmma,
                             cudaFuncAttributeMaxDynamicSharedMemorySize,
                             SMEM_TOTAL);
        attr_done = true;
    }

    prep_x <<<2048, 256>>>(x);
    prep_w1<<<32,   256>>>(W1);
    prep_lt<<<128,  256>>>(Lv);
    prep_w2<<<10,   256>>>(W2, qb);
    koopman_hmma<<<NCTA, NT, SMEM_TOTAL>>>(b1, qc, out);
}

// round 10
// speedup vs baseline: 5.0563x; 1.1000x over previous
#include <cuda_runtime.h>
#include <cuda_bf16.h>
#include <stdint.h>

#define BATCH 32768
#define TM    64
#define NCTA  512
#define NT    256

// ---- smem byte offsets ----
#define PHIH 0            // phi_hi [64][512] bf16, 1024B rows, swizzled
#define PHIL 65536
#define XH   131072       // phase1: x_hi [64][128] bf16, 256B rows
#define XL   147456
#define WH   163840       // phase1: W1 staging hi (128 rows x 256B)
#define WL   196608       // phase1: W1 staging lo
#define BUFA 131072       // phase3 ping buffer (hi 16K + lo 16K)
#define BUFB 163840       // phase3 pong buffer (hi 16K + lo 16K)
#define W2LO (WH + 10240) // phase-2 lo region (40 rows x 256B)
#define YS   229376       // y[64] float
#define SMEM_TOTAL 229632

// ---- pre-split smem-image operand tiles (device globals: allocation-free) ----
__device__ uint4 g_xh[524288], g_xl[524288];   // [512 blk][16KB image]
__device__ uint4 g_w1h[8192],  g_w1l[8192];    // [4 chunk][32KB image]
__device__ uint4 g_lth[32768], g_ltl[32768];   // [16 tile][32KB image] L^T[j][i]
__device__ uint4 g_w2[5120];                   // [4 chunk][hi 10KB | lo 10KB]

// XOR swizzle: 16B unit index ^ (row & 7); conflict-free ldmatrix
__device__ __forceinline__ uint32_t swu(int row, int unit, int rb) {
    return (uint32_t)(row * rb) + (uint32_t)((unit ^ (row & 7)) << 4);
}
__device__ __forceinline__ void split_bf16(float v, uint32_t& h, uint32_t& l) {
    __nv_bfloat16 hb = __float2bfloat16(v);
    float r = v - __bfloat162float(hb);
    __nv_bfloat16 lb = __float2bfloat16(r);
    h = (uint32_t)__bfloat16_as_ushort(hb);
    l = (uint32_t)__bfloat16_as_ushort(lb);
}
__device__ __forceinline__ void split8(const float* v, uint4& hv, uint4& lv) {
    uint32_t hw[8], lw[8];
    #pragma unroll
    for (int q = 0; q < 8; ++q) split_bf16(v[q], hw[q], lw[q]);
    hv = make_uint4(hw[0] | (hw[1] << 16), hw[2] | (hw[3] << 16),
                    hw[4] | (hw[5] << 16), hw[6] | (hw[7] << 16));
    lv = make_uint4(lw[0] | (lw[1] << 16), lw[2] | (lw[3] << 16),
                    lw[4] | (lw[5] << 16), lw[6] | (lw[7] << 16));
}

// ---- PTX wrappers (baseline ISA, compiles for plain sm_103) ----
__device__ __forceinline__ void ldsm_x4(uint32_t a, uint32_t* r) {
    asm volatile("ldmatrix.sync.aligned.m8n8.x4.shared.b16 {%0,%1,%2,%3}, [%4];"
                 : "=r"(r[0]), "=r"(r[1]), "=r"(r[2]), "=r"(r[3]) : "r"(a));
}
__device__ __forceinline__ void ldsm_x2(uint32_t a, uint32_t* r) {
    asm volatile("ldmatrix.sync.aligned.m8n8.x2.shared.b16 {%0,%1}, [%2];"
                 : "=r"(r[0]), "=r"(r[1]) : "r"(a));
}
__device__ __forceinline__ void mma16816(float* c, const uint32_t* a, const uint32_t* b) {
    asm volatile("mma.sync.aligned.m16n8k16.row.col.f32.bf16.bf16.f32 "
                 "{%0,%1,%2,%3}, {%4,%5,%6,%7}, {%8,%9}, {%0,%1,%2,%3};"
                 : "+f"(c[0]), "+f"(c[1]), "+f"(c[2]), "+f"(c[3])
                 : "r"(a[0]), "r"(a[1]), "r"(a[2]), "r"(a[3]), "r"(b[0]), "r"(b[1]));
}
__device__ __forceinline__ void cp16(uint32_t dst, const void* src) {
    asm volatile("cp.async.ca.shared.global [%0], [%1], 16;" :: "r"(dst), "l"(src));
}
#define CP_COMMIT() asm volatile("cp.async.commit_group;" ::: "memory")
#define CP_WAIT0()  asm volatile("cp.async.wait_group 0;" ::: "memory")
#define CP_WAIT1()  asm volatile("cp.async.wait_group 1;" ::: "memory")

// ---- prep kernels ----
__global__ void prep_x(const float* __restrict__ x) {
    int u = blockIdx.x * 256 + threadIdx.x;          // 524288 units
    int rg = u >> 4, c0 = (u & 15) << 3;
    const float* s = x + (size_t)rg * 128 + c0;
    float v[8];
    #pragma unroll
    for (int q = 0; q < 8; ++q) v[q] = s[q];
    uint4 hv, lv; split8(v, hv, lv);
    uint32_t off = ((uint32_t)((rg >> 6) * 16384) + swu(rg & 63, c0 >> 3, 256)) >> 4;
    g_xh[off] = hv; g_xl[off] = lv;
}
__global__ void prep_rest(const float* __restrict__ W1, const float* __restrict__ Lv,
                          const float* __restrict__ W2, const float* __restrict__ qb) {
    int b = blockIdx.x;
    if (b < 32) {                                     // ---- W1 ----
        int u = b * 256 + threadIdx.x;                // 8192 units
        int h = u >> 4, c0 = (u & 15) << 3;
        const float* s = W1 + (size_t)h * 128 + c0;
        float v[8];
        #pragma unroll
        for (int q = 0; q < 8; ++q) v[q] = s[q];
        uint4 hv, lv; split8(v, hv, lv);
        uint32_t off = ((uint32_t)((h >> 7) * 32768) + swu(h & 127, c0 >> 3, 256)) >> 4;
        g_w1h[off] = hv; g_w1l[off] = lv;
    } else if (b < 160) {                             // ---- L^T tiles ----
        int u = (b - 32) * 256 + threadIdx.x;         // 32768 units
        int tile = u >> 11;
        int r = (u >> 4) & 127, c0 = (u & 15) << 3;
        int t = tile >> 2, kt = tile & 3;
        int j = t * 128 + r;
        float v[8];
        #pragma unroll
        for (int q = 0; q < 8; ++q) {
            int i = kt * 128 + c0 + q;
            v[q] = (j <= i) ? Lv[i * (i + 1) / 2 + j] : 0.0f;
        }
        uint4 hv, lv; split8(v, hv, lv);
        uint32_t off = ((uint32_t)(tile * 32768) + swu(r, c0 >> 3, 256)) >> 4;
        g_lth[off] = hv; g_ltl[off] = lv;
    } else {                                          // ---- W2ext ----
        int u = (b - 160) * 256 + threadIdx.x;        // 2560 units
        if (u >= 2560) return;
        int chunk = u / 640, g = u - chunk * 640;
        int o = g >> 4, c0 = (g & 15) << 3;
        float v[8];
        #pragma unroll
        for (int q = 0; q < 8; ++q) {
            int i = chunk * 128 + c0 + q;
            v[q] = (o < 32) ? W2[(size_t)o * 512 + i] : ((o == 32) ? qb[i] : 0.0f);
        }
        uint4 hv, lv; split8(v, hv, lv);
        uint32_t off = (uint32_t)(chunk * 1280) + (swu(o, c0 >> 3, 256) >> 4);
        g_w2[off] = hv; g_w2[off + 640] = lv;
    }
}

// ---- main fused kernel ----
__global__ void __launch_bounds__(NT, 1)
koopman_hmma(const float* __restrict__ b1, const float* __restrict__ qc,
             float* __restrict__ out) {
    extern __shared__ char sm[];
    const int tid = threadIdx.x, lane = tid & 31, warp = tid >> 5;
    const int blk = blockIdx.x, r0 = blk * TM;
    const int mw = warp & 3, nh = warp >> 2;
    const int m0 = mw * 16;
    const int arow = m0 + (lane & 7) + (((lane >> 3) & 1) << 3);
    const int acb  = lane >> 4;
    // B-operand x4 pairing: lane group m = lane>>3 -> matrix m
    const int brow4 = lane & 7;
    const int bm    = lane >> 3;
    const int bku   = bm & 1;          // k-unit select within pair
    const int bno   = (bm >> 1) << 3;  // +8 rows for second n-tile
    const int r1 = m0 + (lane >> 2), r2 = r1 + 8;
    const uint32_t smb = (uint32_t)__cvta_generic_to_shared(sm);
    float* ys = (float*)(sm + YS);

    if (tid < TM) ys[tid] = 0.0f;
    {   // stage x hi/lo via cp.async
        const uint4* sxh = g_xh + (size_t)blk * 1024;
        const uint4* sxl = g_xl + (size_t)blk * 1024;
        for (int i = tid; i < 1024; i += NT) {
            cp16(smb + XH + i * 16, sxh + i);
            cp16(smb + XL + i * 16, sxl + i);
        }
        CP_COMMIT();
    }

    // ============ Phase 1: phi = tanh(x @ W1^T + b1) ============
    for (int c = 0; c < 4; ++c) {
        if (c) __syncthreads();     // phi writes of previous chunk done (distinct regions, but keeps W buffer safe)
        {
            const uint4* swh = g_w1h + c * 2048;
            const uint4* swl = g_w1l + c * 2048;
            for (int i = tid; i < 2048; i += NT) {
                cp16(smb + WH + i * 16, swh + i);
                cp16(smb + WL + i * 16, swl + i);
            }
            CP_COMMIT(); CP_WAIT0();
        }
        __syncthreads();

        float acc[8][4];
        #pragma unroll
        for (int nt = 0; nt < 8; ++nt)
            #pragma unroll
            for (int q = 0; q < 4; ++q) acc[nt][q] = 0.0f;

        #pragma unroll 2
        for (int k8 = 0; k8 < 8; ++k8) {
            const int ku = k8 * 2;
            uint32_t ah[4], al[4];
            uint32_t ao = smb + XH + swu(arow, ku + acb, 256);
            ldsm_x4(ao, ah);
            ldsm_x4(ao + (XL - XH), al);
            #pragma unroll
            for (int ntp = 0; ntp < 4; ++ntp) {
                int bn = nh * 64 + ntp * 16 + bno + brow4;
                uint32_t bo = smb + WH + swu(bn, ku + bku, 256);
                uint32_t bh4[4], bl4[4];
                ldsm_x4(bo, bh4);
                ldsm_x4(bo + (WL - WH), bl4);
                mma16816(acc[2 * ntp],     ah, bh4);
                mma16816(acc[2 * ntp],     al, bh4);
                mma16816(acc[2 * ntp],     ah, bl4);
                mma16816(acc[2 * ntp + 1], ah, bh4 + 2);
                mma16816(acc[2 * ntp + 1], al, bh4 + 2);
                mma16816(acc[2 * ntp + 1], ah, bl4 + 2);
            }
        }
        // epilogue: +b1, tanh, split, store phi hi/lo
        #pragma unroll
        for (int nt = 0; nt < 8; ++nt) {
            int h = c * 128 + nh * 64 + nt * 8 + (lane & 3) * 2;
            float bb0 = __ldg(b1 + h), bb1 = __ldg(b1 + h + 1);
            float v0 = tanhf(acc[nt][0] + bb0), v1 = tanhf(acc[nt][1] + bb1);
            float v2 = tanhf(acc[nt][2] + bb0), v3 = tanhf(acc[nt][3] + bb1);
            uint32_t h0, l0, h1, l1;
            uint32_t sub = ((uint32_t)(h & 7)) << 1;
            split_bf16(v0, h0, l0); split_bf16(v1, h1, l1);
            *(uint32_t*)(sm + PHIH + swu(r1, h >> 3, 1024) + sub) = h0 | (h1 << 16);
            *(uint32_t*)(sm + PHIL + swu(r1, h >> 3, 1024) + sub) = l0 | (l1 << 16);
            split_bf16(v2, h0, l0); split_bf16(v3, h1, l1);
            *(uint32_t*)(sm + PHIH + swu(r2, h >> 3, 1024) + sub) = h0 | (h1 << 16);
            *(uint32_t*)(sm + PHIL + swu(r2, h >> 3, 1024) + sub) = l0 | (l1 << 16);
        }
    }
    __syncthreads();   // phi complete; phase-3 buffers may overwrite x/W regions

    // ============ Phase 3: y = ||phi @ L||^2, half-tile pipelined ============
    // L tile (t,kt) image: 128 rows x 16 units. Half h = units h*8..h*8+7 of
    // each row, repacked to 128B rows in a 16KB hi + 16KB lo half-buffer.
    for (int t = 0; t < 4; ++t) {
        float acc[8][4];
        #pragma unroll
        for (int nt = 0; nt < 8; ++nt)
            #pragma unroll
            for (int q = 0; q < 4; ++q) acc[nt][q] = 0.0f;

        const int nseq = 2 * (4 - t);
        // seq s: kt = t + (s>>1), half = s&1, buffer = s&1
        {   // prologue: stage seq 0 into BUFA
            const uint4* sh = g_lth + (size_t)(t * 4 + t) * 2048;
            const uint4* sl = g_ltl + (size_t)(t * 4 + t) * 2048;
            for (int i = tid; i < 1024; i += NT) {
                int r = i >> 3, uu = i & 7;
                uint32_t d = smb + BUFA + (uint32_t)(r * 128 + uu * 16);
                cp16(d,         sh + r * 16 + uu);
                cp16(d + 16384, sl + r * 16 + uu);
            }
            CP_COMMIT();
        }
        for (int s = 0; s < nseq; ++s) {
            const int kt = t + (s >> 1), half = s & 1;
            if (s + 1 < nseq) {   // prefetch seq s+1 into the other buffer
                const int kt2 = t + ((s + 1) >> 1), h2 = (s + 1) & 1;
                const uint32_t base2 = ((s + 1) & 1) ? BUFB : BUFA;
                const uint4* sh = g_lth + (size_t)(t * 4 + kt2) * 2048;
                const uint4* sl = g_ltl + (size_t)(t * 4 + kt2) * 2048;
                for (int i = tid; i < 1024; i += NT) {
                    int r = i >> 3, uu = i & 7;
                    uint32_t d = smb + base2 + (uint32_t)(r * 128 + uu * 16);
                    cp16(d,         sh + r * 16 + h2 * 8 + uu);
                    cp16(d + 16384, sl + r * 16 + h2 * 8 + uu);
                }
                CP_COMMIT(); CP_WAIT1();
            } else {
                CP_WAIT0();
            }
            __syncthreads();      // current buffer fully visible to all warps

            const uint32_t hb = (s & 1) ? BUFB : BUFA;
            #pragma unroll
            for (int k8l = 0; k8l < 4; ++k8l) {
                const int kuA = kt * 16 + (half * 4 + k8l) * 2;
                uint32_t ah[4], al[4];
                uint32_t ao = smb + PHIH + swu(arow, kuA + acb, 1024);
                ldsm_x4(ao, ah);
                ldsm_x4(ao + (PHIL - PHIH), al);
                #pragma unroll
                for (int ntp = 0; ntp < 4; ++ntp) {
                    int bn = nh * 64 + ntp * 16 + bno + brow4;
                    uint32_t up = (uint32_t)(k8l * 2 + bku);
                    uint32_t bo = smb + hb + (uint32_t)(bn * 128) +
                                  ((up ^ (uint32_t)(bn & 7)) << 4);
                    uint32_t bh4[4], bl4[4];
                    ldsm_x4(bo, bh4);
                    ldsm_x4(bo + 16384, bl4);
                    mma16816(acc[2 * ntp],     ah, bh4);
                    mma16816(acc[2 * ntp],     al, bh4);
                    mma16816(acc[2 * ntp],     ah, bl4);
                    mma16816(acc[2 * ntp + 1], ah, bh4 + 2);
                    mma16816(acc[2 * ntp + 1], al, bh4 + 2);
                    mma16816(acc[2 * ntp + 1], ah, bl4 + 2);
                }
            }
            __syncthreads();      // all reads done before this buffer is overwritten
        }
        float s1 = 0.0f, s2 = 0.0f;
        #pragma unroll
        for (int nt = 0; nt < 8; ++nt) {
            s1 = fmaf(acc[nt][0], acc[nt][0], s1);
            s1 = fmaf(acc[nt][1], acc[nt][1], s1);
            s2 = fmaf(acc[nt][2], acc[nt][2], s2);
            s2 = fmaf(acc[nt][3], acc[nt][3], s2);
        }
        s1 += __shfl_xor_sync(0xffffffffu, s1, 1);
        s1 += __shfl_xor_sync(0xffffffffu, s1, 2);
        s2 += __shfl_xor_sync(0xffffffffu, s2, 1);
        s2 += __shfl_xor_sync(0xffffffffu, s2, 2);
        if ((lane & 3) == 0) { atomicAdd(ys + r1, s1); atomicAdd(ys + r2, s2); }
    }

    // ============ Phase 2: [pi | phi.qb] = phi @ W2ext^T ============
    const int ntc = nh ? 2 : 3;
    float acc2[3][4];
    #pragma unroll
    for (int q = 0; q < 3; ++q)
        #pragma unroll
        for (int e = 0; e < 4; ++e) acc2[q][e] = 0.0f;

    for (int kt = 0; kt < 4; ++kt) {
        __syncthreads();
        {
            const uint4* s = g_w2 + kt * 1280;
            for (int i = tid; i < 640; i += NT) {
                cp16(smb + WH   + i * 16, s + i);
                cp16(smb + W2LO + i * 16, s + 640 + i);
            }
            CP_COMMIT(); CP_WAIT0();
        }
        __syncthreads();
        #pragma unroll 2
        for (int k8 = 0; k8 < 8; ++k8) {
            const int kuA = (kt * 128 + k8 * 16) >> 3;
            const int kuB = k8 * 2;
            uint32_t ah[4], al[4];
            uint32_t ao = smb + PHIH + swu(arow, kuA + acb, 1024);
            ldsm_x4(ao, ah);
            ldsm_x4(ao + (PHIL - PHIH), al);
            #pragma unroll
            for (int q = 0; q < 3; ++q) {
                if (q >= ntc) break;
                int tile = nh ? 3 + q : q;
                int bn = tile * 8 + brow4 + ((bm & 2) ? 0 : 0);  // x2 path: lanes 0-15 used
                uint32_t bo = smb + WH + swu(tile * 8 + (lane & 7), kuB + ((lane >> 3) & 1), 256);
                uint32_t bh[2], bl[2];
                ldsm_x2(bo, bh);
                ldsm_x2(bo + (W2LO - WH), bl);
                mma16816(acc2[q], ah, bh);
                mma16816(acc2[q], al, bh);
                mma16816(acc2[q], ah, bl);
                (void)bn;
            }
        }
    }
    __syncthreads();
    #pragma unroll
    for (int q = 0; q < 3; ++q) {
        if (q >= ntc) break;
        int tile = nh ? 3 + q : q;
        int o = tile * 8 + (lane & 3) * 2;
        if (tile < 4) {
            out[(size_t)(r0 + r1) * 32 + o]     = acc2[q][0];
            out[(size_t)(r0 + r1) * 32 + o + 1] = acc2[q][1];
            out[(size_t)(r0 + r2) * 32 + o]     = acc2[q][2];
            out[(size_t)(r0 + r2) * 32 + o + 1] = acc2[q][3];
        } else if ((lane & 3) == 0) {
            float qcv = __ldg(qc);
            out[(size_t)BATCH * 32 + r0 + r1] = ys[r1] + acc2[q][0] + qcv;
            out[(size_t)BATCH * 32 + r0 + r2] = ys[r2] + acc2[q][2] + qcv;
        }
    }
}

// ---------------------------------------------------------------------------
extern "C" void kernel_launch(void* const* d_in, const int* in_sizes, int n_in,
                              void* d_out, int out_size) {
    const float* x  = (const float*)d_in[0];
    const float* W1 = (const float*)d_in[1];
    const float* b1 = (const float*)d_in[2];
    const float* W2 = (const float*)d_in[3];
    const float* Lv = (const float*)d_in[4];
    const float* qb = (const float*)d_in[5];
    const float* qc = (const float*)d_in[6];
    float* out = (float*)d_out;

    // Attribute set only on the (non-captured) first call — calling runtime
    // APIs during graph capture kills the capture (R5/R7 lesson).
    static bool attr_done = false;
    if (!attr_done) {
        cudaFuncSetAttribute(koopman_hmma,
                             cudaFuncAttributeMaxDynamicSharedMemorySize,
                             SMEM_TOTAL);
        attr_done = true;
    }

    prep_x   <<<2048, 256>>>(x);
    prep_rest<<<170,  256>>>(W1, Lv, W2, qb);
    koopman_hmma<<<NCTA, NT, SMEM_TOTAL>>>(b1, qc, out);
}